// round 4
// baseline (speedup 1.0000x reference)
#include <cuda_runtime.h>

// GARCH(1,1): h[t] = (omega + alpha*r[t-1]^2) + beta*h[t-1], h[0] = var(r, ddof=1)
// out[0..n) = sqrt(h), out[n..2n) = h
//
// Register/shuffle-only design: beta<1 makes the recurrence contractive
// (beta^256 ~ 8e-19 < fp32 ulp), so each WARP independently processes a
// contiguous 2048-output span with a 256-element warm-up halo, streaming
// 128-element segments (4 consecutive elements per lane via float4):
//   LDG.128 -> shfl boundary shift -> 3-FMA local chain ->
//   5-step Kogge-Stone shuffle scan (multipliers beta^(4*2^k)) ->
//   carry apply (lane constant beta^(4*lane)) -> sqrt.approx -> 2x STG.128.
// No shared memory, no __syncthreads in the mainloop.
// True h[t] = h_hat[t] + beta^t*h0 (linearity): the h0 term only matters for
// t < ~100 and is patched by the last block (ticket), which also reduces the
// variance partials.

#define TPB    256
#define WARPS  (TPB/32)
#define SEG    128               // elements per warp-segment (4 per lane)
#define HSEG   2                 // halo segments (256 elements)
#define OSEG   16                // output segments per warp
#define TSEG   (HSEG + OSEG)     // 18
#define WOUT   (OSEG * SEG)      // 2048 outputs per warp
#define BOUT   (WARPS * WOUT)    // 16384 outputs per block
#define HALO   (HSEG * SEG)      // 256
#define FIXN   256
#define MAXT   8192              // max tiles (partial slots)

__device__ double   g_psum[MAXT];
__device__ double   g_psumsq[MAXT];
__device__ unsigned g_ticket = 0;

__device__ __forceinline__ float fsqrt_ap(float x) {
    float y; asm("sqrt.approx.f32 %0, %1;" : "=f"(y) : "f"(x)); return y;
}

__global__ void __launch_bounds__(TPB)
garch_fused(const float* __restrict__ r,
            const float* __restrict__ omega_p,
            const float* __restrict__ alpha_p,
            const float* __restrict__ beta_p,
            float* __restrict__ out,
            int n, int ntiles, int write_h)
{
    __shared__ float    swsum[WARPS], swq[WARPS];
    __shared__ unsigned s_ticket;
    __shared__ float    sh0;
    __shared__ double   red[TPB], red2[TPB];

    const int tid  = threadIdx.x;
    const int wid  = tid >> 5;
    const int lane = tid & 31;
    const unsigned FULL = 0xFFFFFFFFu;

    const float omega = *omega_p;
    const float alpha = *alpha_p;
    const float beta  = *beta_p;

    const float beta2 = beta * beta;
    const float beta3 = beta2 * beta;
    const float beta4 = beta2 * beta2;
    const float M0 = beta4;            // scan multipliers beta^(4*2^k)
    const float M1 = M0 * M0;          // beta^8
    const float M2 = M1 * M1;          // beta^16
    const float M3 = M2 * M2;          // beta^32
    const float M4 = M3 * M3;          // beta^64

    // lanepow = beta^(4*lane)
    float lanepow = 1.0f;
    { float p = beta4; int e = lane;
      while (e) { if (e & 1) lanepow *= p; p *= p; e >>= 1; } }

    float vs = 0.0f, vq = 0.0f;

    for (int bb = blockIdx.x; bb < ntiles; bb += gridDim.x) {
        const long long W0 = ((long long)bb * WARPS + wid) * WOUT;
        float c_prev = 0.0f;          // h at segment start - 1
        float wprev  = 0.0f;          // r value one before this segment

        #pragma unroll 2
        for (int s = 0; s < TSEG; ++s) {
            const long long t_base = W0 - HALO + (long long)s * SEG;
            const long long tl     = t_base + 4 * lane;   // this lane's first t
            const bool is_out  = (s >= HSEG);
            const bool fastseg = (t_base >= 0) && (t_base + SEG <= (long long)n);

            float4 v;
            if (fastseg) {
                v = *(const float4*)(r + tl);             // 16B aligned
            } else {
                v.x = (tl + 0 >= 0 && tl + 0 < n) ? r[tl + 0] : 0.0f;
                v.y = (tl + 1 >= 0 && tl + 1 < n) ? r[tl + 1] : 0.0f;
                v.z = (tl + 2 >= 0 && tl + 2 < n) ? r[tl + 2] : 0.0f;
                v.w = (tl + 3 >= 0 && tl + 3 < n) ? r[tl + 3] : 0.0f;
            }

            // boundary shift: driver of element t is r[t-1]
            float pw   = __shfl_up_sync(FULL, v.w, 1);
            float prev = (lane == 0) ? wprev : pw;
            wprev = __shfl_sync(FULL, v.w, 31);

            float rr0 = prev * prev;
            float rr1 = v.x * v.x, rr2 = v.y * v.y, rr3 = v.z * v.z;
            float b0 = fmaf(alpha, rr0, omega);
            float b1 = fmaf(alpha, rr1, omega);
            float b2 = fmaf(alpha, rr2, omega);
            float b3 = fmaf(alpha, rr3, omega);
            if (!fastseg) {                               // invalid t: driver 0
                if (!(tl + 0 >= 1 && tl + 0 < n)) b0 = 0.0f;
                if (!(tl + 1 >= 1 && tl + 1 < n)) b1 = 0.0f;
                if (!(tl + 2 >= 1 && tl + 2 < n)) b2 = 0.0f;
                if (!(tl + 3 >= 1 && tl + 3 < n)) b3 = 0.0f;
            } else if (t_base == 0 && lane == 0) {
                b0 = 0.0f;                                // t=0: h_hat[0] = 0
            }

            // local 4-chain from zero state
            float p0 = b0;
            float p1 = fmaf(beta, p0, b1);
            float p2 = fmaf(beta, p1, b2);
            float p3 = fmaf(beta, p2, b3);

            // Kogge-Stone over lane ends: S_l = E_l + beta^4 * S_{l-1}
            float S = p3, t1;
            t1 = __shfl_up_sync(FULL, S, 1);  S = fmaf(M0, (lane >= 1)  ? t1 : 0.0f, S);
            t1 = __shfl_up_sync(FULL, S, 2);  S = fmaf(M1, (lane >= 2)  ? t1 : 0.0f, S);
            t1 = __shfl_up_sync(FULL, S, 4);  S = fmaf(M2, (lane >= 4)  ? t1 : 0.0f, S);
            t1 = __shfl_up_sync(FULL, S, 8);  S = fmaf(M3, (lane >= 8)  ? t1 : 0.0f, S);
            t1 = __shfl_up_sync(FULL, S, 16); S = fmaf(M4, (lane >= 16) ? t1 : 0.0f, S);

            // prefix at this lane's start, including previous-segment carry
            float Sp = __shfl_up_sync(FULL, S, 1);
            float G  = fmaf(lanepow, c_prev, (lane >= 1) ? Sp : 0.0f);

            float h0 = fmaf(beta,  G, p0);
            float h1 = fmaf(beta2, G, p1);
            float h2 = fmaf(beta3, G, p2);
            float h3 = fmaf(beta4, G, p3);
            c_prev = __shfl_sync(FULL, h3, 31);

            if (is_out) {
                if (fastseg) {
                    float rrw = v.w * v.w;
                    vs += (v.x + v.y) + (v.z + v.w);
                    vq += (rr1 + rr2) + (rr3 + rrw);
                    *(float4*)(out + tl) =
                        make_float4(fsqrt_ap(h0), fsqrt_ap(h1),
                                    fsqrt_ap(h2), fsqrt_ap(h3));
                    if (write_h)
                        *(float4*)(out + n + tl) = make_float4(h0, h1, h2, h3);
                } else {
                    float hv[4] = {h0, h1, h2, h3};
                    float rv[4] = {v.x, v.y, v.z, v.w};
                    #pragma unroll
                    for (int e = 0; e < 4; ++e) {
                        long long t = tl + e;
                        if (t >= 0 && t < n) {
                            vs += rv[e]; vq = fmaf(rv[e], rv[e], vq);
                            out[t] = fsqrt_ap(hv[e]);
                            if (write_h) out[(long long)n + t] = hv[e];
                        }
                    }
                }
            }
        }

        // per-tile variance partial (deterministic)
        float tvs = vs, tvq = vq; vs = 0.0f; vq = 0.0f;
        #pragma unroll
        for (int off = 16; off; off >>= 1) {
            tvs += __shfl_down_sync(FULL, tvs, off);
            tvq += __shfl_down_sync(FULL, tvq, off);
        }
        if (lane == 0) { swsum[wid] = tvs; swq[wid] = tvq; }
        __syncthreads();
        if (tid == 0) {
            double a = 0.0, q = 0.0;
            #pragma unroll
            for (int w = 0; w < WARPS; ++w) { a += (double)swsum[w]; q += (double)swq[w]; }
            int slot = (bb < MAXT) ? bb : (MAXT - 1);
            g_psum[slot]   = a;
            g_psumsq[slot] = q;
        }
        __syncthreads();
    }

    // ---- ticket: last block reduces partials and patches the h0 term ----
    __threadfence();
    if (tid == 0) s_ticket = atomicAdd(&g_ticket, 1u);
    __syncthreads();
    if (s_ticket != (unsigned)(gridDim.x - 1)) return;

    if (tid == 0) g_ticket = 0;                  // reset for graph replays
    __threadfence();

    const int nslots = (ntiles < MAXT) ? ntiles : MAXT;
    {
        double a = 0.0, q = 0.0;
        for (int i = tid; i < nslots; i += TPB) { a += g_psum[i]; q += g_psumsq[i]; }
        red[tid] = a; red2[tid] = q;
    }
    __syncthreads();
    for (int s = TPB / 2; s; s >>= 1) {
        if (tid < s) { red[tid] += red[tid + s]; red2[tid] += red2[tid + s]; }
        __syncthreads();
    }
    if (tid == 0) {
        double Ssum = red[0], Q = red2[0];
        sh0 = (float)((Q - Ssum * Ssum / (double)n) / (double)(n - 1));
    }
    __syncthreads();

    const float h0v = sh0;
    const int   lim = (FIXN < n) ? FIXN : n;
    if (write_h) {
        // h[t] = h_hat[t] + beta^t * h0; h_hat already stored in out[n+t]
        for (int t = tid; t < lim; t += TPB) {
            float bp = 1.0f, bb2 = beta; int e = t;
            while (e) { if (e & 1) bp *= bb2; bb2 *= bb2; e >>= 1; }
            float hh = (t == 0) ? h0v : fmaf(bp, h0v, out[(long long)n + t]);
            out[(long long)n + t] = hh;
            out[t] = fsqrt_ap(hh);
        }
    } else {
        if (tid == 0) {                          // fallback: serial exact prefix
            float h = h0v;
            out[0] = fsqrt_ap(h);
            for (int t = 1; t < lim; ++t) {
                float rv = r[t - 1];
                h = fmaf(beta, h, fmaf(alpha * rv, rv, omega));
                out[t] = fsqrt_ap(h);
            }
        }
    }
}

extern "C" void kernel_launch(void* const* d_in, const int* in_sizes, int n_in,
                              void* d_out, int out_size)
{
    const float* r  = (const float*)d_in[0];
    const float* om = (const float*)d_in[1];
    const float* al = (const float*)d_in[2];
    const float* be = (const float*)d_in[3];
    float* out = (float*)d_out;

    const int n = in_sizes[0];
    const int write_h = (out_size >= 2 * n) ? 1 : 0;

    int ntiles = (n + BOUT - 1) / BOUT;
    if (ntiles < 1) ntiles = 1;
    int grid = (ntiles < MAXT) ? ntiles : MAXT;

    garch_fused<<<grid, TPB>>>(r, om, al, be, out, n, ntiles, write_h);
}

// round 5
// speedup vs baseline: 1.0319x; 1.0319x over previous
#include <cuda_runtime.h>

// GARCH(1,1): h[t] = (omega + alpha*r[t-1]^2) + beta*h[t-1], h[0] = var(r, ddof=1)
// out[0..n) = sqrt(h), out[n..2n) = h
//
// Register/shuffle-only, software-pipelined. beta<1 => contractive recurrence
// (beta^256 ~ 8e-19 < fp32 ulp): each WARP independently produces a 2048-output
// span with a 256-element warm-up halo, streaming 256-element segments
// (8 consecutive elements per lane via 2x float4, prefetched one segment ahead):
//   prefetch LDGs -> shfl boundary shift -> 7-FMA local chain ->
//   5-step Kogge-Stone shuffle scan (multipliers beta^(8*2^k)) ->
//   carry apply -> sqrt.approx -> 4x STG.128.
// True h[t] = h_hat[t] + beta^t*h0 (linearity): the h0 term only matters for
// t < ~100 and is patched by the last block (ticket), which also reduces the
// fp32 variance partials.

#define TPB    256
#define WARPS  (TPB/32)
#define EPL    8                 // elements per lane per segment
#define SEG    (32*EPL)          // 256 elements per warp-segment
#define HSEG   1                 // halo segments (256 elements)
#define OSEG   8                 // output segments per warp
#define TSEG   (HSEG + OSEG)     // 9
#define WOUT   (OSEG * SEG)      // 2048 outputs per warp
#define BOUT   (WARPS * WOUT)    // 16384 outputs per block
#define HALO   (HSEG * SEG)      // 256
#define FIXN   256
#define MAXB   1024              // max blocks (partial slots)

__device__ double   g_psum[MAXB];
__device__ double   g_psumsq[MAXB];
__device__ unsigned g_ticket = 0;

__device__ __forceinline__ float fsqrt_ap(float x) {
    float y; asm("sqrt.approx.f32 %0, %1;" : "=f"(y) : "f"(x)); return y;
}

__device__ __forceinline__ void load_seg(const float* __restrict__ r, int n,
                                         long long tl, bool fastseg,
                                         float4& a, float4& b)
{
    if (fastseg) {
        a = *(const float4*)(r + tl);
        b = *(const float4*)(r + tl + 4);
    } else {
        float* pa = (float*)&a; float* pb = (float*)&b;
        #pragma unroll
        for (int e = 0; e < 4; ++e) {
            long long t1 = tl + e, t2 = tl + 4 + e;
            pa[e] = (t1 >= 0 && t1 < n) ? r[t1] : 0.0f;
            pb[e] = (t2 >= 0 && t2 < n) ? r[t2] : 0.0f;
        }
    }
}

__global__ void __launch_bounds__(TPB)
garch_fused(const float* __restrict__ r,
            const float* __restrict__ omega_p,
            const float* __restrict__ alpha_p,
            const float* __restrict__ beta_p,
            float* __restrict__ out,
            int n, int ntiles, int write_h)
{
    __shared__ float    swsum[WARPS], swq[WARPS];
    __shared__ unsigned s_ticket;
    __shared__ float    sh0;
    __shared__ double   red[TPB], red2[TPB];

    const int tid  = threadIdx.x;
    const int wid  = tid >> 5;
    const int lane = tid & 31;
    const unsigned FULL = 0xFFFFFFFFu;

    const float omega = *omega_p;
    const float alpha = *alpha_p;
    const float beta  = *beta_p;

    // beta powers
    float bp[9];                       // bp[j] = beta^j
    bp[0] = 1.0f;
    #pragma unroll
    for (int j = 1; j <= 8; ++j) bp[j] = bp[j - 1] * beta;
    const float M0 = bp[8];            // beta^8
    const float M1 = M0 * M0;          // beta^16
    const float M2 = M1 * M1;          // beta^32
    const float M3 = M2 * M2;          // beta^64
    const float M4 = M3 * M3;          // beta^128

    // lanepow = beta^(8*lane)
    float lanepow = 1.0f;
    { float p = bp[8]; int e = lane;
      while (e) { if (e & 1) lanepow *= p; p *= p; e >>= 1; } }

    float vs = 0.0f, vq = 0.0f;        // variance partials (whole block's work)

    for (int bb = blockIdx.x; bb < ntiles; bb += gridDim.x) {
        const long long W0 = ((long long)bb * WARPS + wid) * WOUT;
        float c_prev = 0.0f;           // h at segment start - 1
        float wprev  = 0.0f;           // r one before this segment

        // prefetch segment 0
        float4 a0, a1;
        {
            long long t_base = W0 - HALO;
            long long tl = t_base + (long long)EPL * lane;
            bool fs = (t_base >= 0) && (t_base + SEG <= (long long)n);
            load_seg(r, n, tl, fs, a0, a1);
        }

        #pragma unroll
        for (int s = 0; s < TSEG; ++s) {
            const long long t_base = W0 - HALO + (long long)s * SEG;
            const long long tl     = t_base + (long long)EPL * lane;
            const bool is_out  = (s >= HSEG);
            const bool fastseg = (t_base >= 0) && (t_base + SEG <= (long long)n);

            // prefetch next segment
            float4 n0, n1;
            if (s + 1 < TSEG) {
                long long tb2 = t_base + SEG;
                long long tl2 = tb2 + (long long)EPL * lane;
                bool fs2 = (tb2 >= 0) && (tb2 + SEG <= (long long)n);
                load_seg(r, n, tl2, fs2, n0, n1);
            }

            float x0 = a0.x, x1 = a0.y, x2 = a0.z, x3 = a0.w;
            float x4 = a1.x, x5 = a1.y, x6 = a1.z, x7 = a1.w;

            // boundary shift: driver of element t is r[t-1]
            float pw   = __shfl_up_sync(FULL, x7, 1);
            float prev = (lane == 0) ? wprev : pw;
            wprev = __shfl_sync(FULL, x7, 31);

            float q0 = prev * prev;
            float q1 = x0 * x0, q2 = x1 * x1, q3 = x2 * x2, q4 = x3 * x3;
            float q5 = x4 * x4, q6 = x5 * x5, q7 = x6 * x6;

            float d0 = fmaf(alpha, q0, omega);
            float d1 = fmaf(alpha, q1, omega);
            float d2 = fmaf(alpha, q2, omega);
            float d3 = fmaf(alpha, q3, omega);
            float d4 = fmaf(alpha, q4, omega);
            float d5 = fmaf(alpha, q5, omega);
            float d6 = fmaf(alpha, q6, omega);
            float d7 = fmaf(alpha, q7, omega);

            if (!fastseg) {            // out-of-range t: driver = 0
                if (!(tl + 0 >= 1 && tl + 0 < n)) d0 = 0.0f;
                if (!(tl + 1 >= 1 && tl + 1 < n)) d1 = 0.0f;
                if (!(tl + 2 >= 1 && tl + 2 < n)) d2 = 0.0f;
                if (!(tl + 3 >= 1 && tl + 3 < n)) d3 = 0.0f;
                if (!(tl + 4 >= 1 && tl + 4 < n)) d4 = 0.0f;
                if (!(tl + 5 >= 1 && tl + 5 < n)) d5 = 0.0f;
                if (!(tl + 6 >= 1 && tl + 6 < n)) d6 = 0.0f;
                if (!(tl + 7 >= 1 && tl + 7 < n)) d7 = 0.0f;
            } else if (t_base == 0 && lane == 0) {
                d0 = 0.0f;             // t=0: h_hat[0] = 0
            }

            // local 8-chain from zero state
            float p0 = d0;
            float p1 = fmaf(beta, p0, d1);
            float p2 = fmaf(beta, p1, d2);
            float p3 = fmaf(beta, p2, d3);
            float p4 = fmaf(beta, p3, d4);
            float p5 = fmaf(beta, p4, d5);
            float p6 = fmaf(beta, p5, d6);
            float p7 = fmaf(beta, p6, d7);

            // Kogge-Stone over lane ends: S_l = E_l + beta^8 * S_{l-1}
            float S = p7, t1;
            t1 = __shfl_up_sync(FULL, S, 1);  S = fmaf(M0, (lane >= 1)  ? t1 : 0.0f, S);
            t1 = __shfl_up_sync(FULL, S, 2);  S = fmaf(M1, (lane >= 2)  ? t1 : 0.0f, S);
            t1 = __shfl_up_sync(FULL, S, 4);  S = fmaf(M2, (lane >= 4)  ? t1 : 0.0f, S);
            t1 = __shfl_up_sync(FULL, S, 8);  S = fmaf(M3, (lane >= 8)  ? t1 : 0.0f, S);
            t1 = __shfl_up_sync(FULL, S, 16); S = fmaf(M4, (lane >= 16) ? t1 : 0.0f, S);

            // prefix at this lane's start + previous-segment carry
            float Sp = __shfl_up_sync(FULL, S, 1);
            float G  = fmaf(lanepow, c_prev, (lane >= 1) ? Sp : 0.0f);

            float h0 = fmaf(bp[1], G, p0);
            float h1 = fmaf(bp[2], G, p1);
            float h2 = fmaf(bp[3], G, p2);
            float h3 = fmaf(bp[4], G, p3);
            float h4 = fmaf(bp[5], G, p4);
            float h5 = fmaf(bp[6], G, p5);
            float h6 = fmaf(bp[7], G, p6);
            float h7 = fmaf(bp[8], G, p7);
            c_prev = __shfl_sync(FULL, h7, 31);

            if (is_out) {
                if (fastseg) {
                    float q8 = x7 * x7;
                    vs += ((x0 + x1) + (x2 + x3)) + ((x4 + x5) + (x6 + x7));
                    vq += ((q1 + q2) + (q3 + q4)) + ((q5 + q6) + (q7 + q8));
                    *(float4*)(out + tl)     = make_float4(fsqrt_ap(h0), fsqrt_ap(h1),
                                                           fsqrt_ap(h2), fsqrt_ap(h3));
                    *(float4*)(out + tl + 4) = make_float4(fsqrt_ap(h4), fsqrt_ap(h5),
                                                           fsqrt_ap(h6), fsqrt_ap(h7));
                    if (write_h) {
                        *(float4*)(out + n + tl)     = make_float4(h0, h1, h2, h3);
                        *(float4*)(out + n + tl + 4) = make_float4(h4, h5, h6, h7);
                    }
                } else {
                    float hv[8] = {h0, h1, h2, h3, h4, h5, h6, h7};
                    float xv[8] = {x0, x1, x2, x3, x4, x5, x6, x7};
                    #pragma unroll
                    for (int e = 0; e < 8; ++e) {
                        long long t = tl + e;
                        if (t >= 0 && t < n) {
                            vs += xv[e]; vq = fmaf(xv[e], xv[e], vq);
                            out[t] = fsqrt_ap(hv[e]);
                            if (write_h) out[(long long)n + t] = hv[e];
                        }
                    }
                }
            }

            a0 = n0; a1 = n1;
        }
    }

    // ---- per-block deterministic variance partial ----
    #pragma unroll
    for (int off = 16; off; off >>= 1) {
        vs += __shfl_down_sync(FULL, vs, off);
        vq += __shfl_down_sync(FULL, vq, off);
    }
    if (lane == 0) { swsum[wid] = vs; swq[wid] = vq; }
    __syncthreads();
    if (tid == 0) {
        double a = 0.0, q = 0.0;
        #pragma unroll
        for (int w = 0; w < WARPS; ++w) { a += (double)swsum[w]; q += (double)swq[w]; }
        g_psum[blockIdx.x]   = a;
        g_psumsq[blockIdx.x] = q;
    }
    __syncthreads();

    // ---- ticket: last block reduces partials and patches the h0 term ----
    __threadfence();
    if (tid == 0) s_ticket = atomicAdd(&g_ticket, 1u);
    __syncthreads();
    if (s_ticket != (unsigned)(gridDim.x - 1)) return;

    if (tid == 0) g_ticket = 0;                  // reset for graph replays
    __threadfence();

    {
        double a = 0.0, q = 0.0;
        for (int i = tid; i < (int)gridDim.x; i += TPB) { a += g_psum[i]; q += g_psumsq[i]; }
        red[tid] = a; red2[tid] = q;
    }
    __syncthreads();
    for (int s = TPB / 2; s; s >>= 1) {
        if (tid < s) { red[tid] += red[tid + s]; red2[tid] += red2[tid + s]; }
        __syncthreads();
    }
    if (tid == 0) {
        double Ssum = red[0], Q = red2[0];
        sh0 = (float)((Q - Ssum * Ssum / (double)n) / (double)(n - 1));
    }
    __syncthreads();

    const float h0v = sh0;
    const int   lim = (FIXN < n) ? FIXN : n;
    if (write_h) {
        // h[t] = h_hat[t] + beta^t * h0; h_hat already stored in out[n+t]
        for (int t = tid; t < lim; t += TPB) {
            float pw2 = 1.0f, bb2 = beta; int e = t;
            while (e) { if (e & 1) pw2 *= bb2; bb2 *= bb2; e >>= 1; }
            float hh = (t == 0) ? h0v : fmaf(pw2, h0v, out[(long long)n + t]);
            out[(long long)n + t] = hh;
            out[t] = fsqrt_ap(hh);
        }
    } else {
        if (tid == 0) {                          // fallback: serial exact prefix
            float h = h0v;
            out[0] = fsqrt_ap(h);
            for (int t = 1; t < lim; ++t) {
                float rv = r[t - 1];
                h = fmaf(beta, h, fmaf(alpha * rv, rv, omega));
                out[t] = fsqrt_ap(h);
            }
        }
    }
}

extern "C" void kernel_launch(void* const* d_in, const int* in_sizes, int n_in,
                              void* d_out, int out_size)
{
    const float* r  = (const float*)d_in[0];
    const float* om = (const float*)d_in[1];
    const float* al = (const float*)d_in[2];
    const float* be = (const float*)d_in[3];
    float* out = (float*)d_out;

    const int n = in_sizes[0];
    const int write_h = (out_size >= 2 * n) ? 1 : 0;

    int ntiles = (n + BOUT - 1) / BOUT;
    if (ntiles < 1) ntiles = 1;

    // choose grid so every block gets an equal number of tiles (no wave tail)
    int grid;
    if (ntiles <= 740) {
        grid = ntiles;
    } else {
        int per = (ntiles + 739) / 740;          // tiles per block
        grid = (ntiles + per - 1) / per;
    }
    if (grid > MAXB) grid = MAXB;

    garch_fused<<<grid, TPB>>>(r, om, al, be, out, n, ntiles, write_h);
}